// round 10
// baseline (speedup 1.0000x reference)
#include <cuda_runtime.h>
#include <math.h>

#define T_TOTAL   65536
#define D_IN      128
#define H_DIM     128
#define NUM_HEADS 8
#define G3        384          // 3*H
#define OUT_COLS  (NUM_HEADS * H_DIM)

// Scratch for precomputed input gates ig[h][t][384] (+ slack for prefetch)
__device__ float g_ig[(size_t)NUM_HEADS * T_TOTAL * G3 + G3];

__device__ __forceinline__ void ffma2(unsigned long long& acc,
                                      unsigned long long a,
                                      unsigned long long b) {
    asm("fma.rn.f32x2 %0, %1, %2, %0;" : "+l"(acc) : "l"(a), "l"(b));
}
__device__ __forceinline__ unsigned long long pack2(float lo, float hi) {
    unsigned long long r;
    asm("mov.b64 %0, {%1, %2};" : "=l"(r) : "f"(lo), "f"(hi));
    return r;
}
__device__ __forceinline__ float hsum2(unsigned long long v) {
    float lo, hi;
    asm("mov.b64 {%0, %1}, %2;" : "=f"(lo), "=f"(hi) : "l"(v));
    return lo + hi;
}
__device__ __forceinline__ float fast_sigmoid(float x) {
    float e = __expf(-x);
    return __fdividef(1.f, 1.f + e);
}
// Clamp-free tanh: 1 - 2/(1 + e^{2x}) (validated round 7).
__device__ __forceinline__ float fast_tanh(float x) {
    float e = __expf(2.f * x);
    return fmaf(-2.f, __fdividef(1.f, 1.f + e), 1.f);
}

// ============================================================================
// Kernel 1: ig[h][t][g] = sum_d x[t,d] * Wih[h,g,d] + b[h,g]
// (validated round 7: swizzled A+B tiles, f32x2 FMAs — unchanged)
// ============================================================================
#define WS_F4   33
#define GEMM_SMEM (2 * 128 * WS_F4 * 16)

__global__ void __launch_bounds__(256, 1)
gemm_ig_kernel(const float* __restrict__ x,
               const float* __restrict__ Wih,
               const float* __restrict__ bias) {
    extern __shared__ float sm[];
    float4* sA4 = (float4*)sm;
    float4* sB4 = sA4 + 128 * WS_F4;

    const int tid = threadIdx.x;
    const int h   = blockIdx.z;
    const int g0  = blockIdx.y * 128;
    const int t0  = blockIdx.x * 128;

    const float4* xg = (const float4*)(x + (size_t)t0 * D_IN);
    const float4* wg = (const float4*)(Wih + ((size_t)h * G3 + g0) * D_IN);

    #pragma unroll
    for (int i = 0; i < 16; i++) {
        int idx = i * 256 + tid;
        int m   = idx >> 5;
        int d4  = idx & 31;
        int sw  = (m >> 3) & 7;
        sA4[m * WS_F4 + (d4 ^ sw)] = xg[m * 32 + d4];
        sB4[m * WS_F4 + (d4 ^ sw)] = wg[m * 32 + d4];
    }
    __syncthreads();

    const int lane  = tid & 31, warp = tid >> 5;
    const int mi    = lane & 7, gi   = lane >> 3;
    const int warpM = warp >> 2, warpG = warp & 3;
    const int mBase = warpM * 64 + mi * 8;
    const int gBase = warpG * 32 + gi * 8;
    const int swA   = mi;
    const int swB   = (warpG * 4 + gi) & 7;

    unsigned long long acc[8][8];
    #pragma unroll
    for (int r = 0; r < 8; r++)
        #pragma unroll
        for (int c = 0; c < 8; c++) acc[r][c] = 0ull;

    const ulonglong2* A2 = (const ulonglong2*)sA4;
    const ulonglong2* B2 = (const ulonglong2*)sB4;

    #pragma unroll
    for (int k4 = 0; k4 < 32; k4++) {
        ulonglong2 av[8], bv[8];
        #pragma unroll
        for (int r = 0; r < 8; r++)
            av[r] = A2[(mBase + r) * WS_F4 + (k4 ^ swA)];
        #pragma unroll
        for (int c = 0; c < 8; c++)
            bv[c] = B2[(gBase + c) * WS_F4 + (k4 ^ swB)];
        #pragma unroll
        for (int r = 0; r < 8; r++)
            #pragma unroll
            for (int c = 0; c < 8; c++) {
                ffma2(acc[r][c], av[r].x, bv[c].x);
                ffma2(acc[r][c], av[r].y, bv[c].y);
            }
    }

    float bb[8];
    #pragma unroll
    for (int c = 0; c < 8; c++)
        bb[c] = bias[(size_t)h * G3 + g0 + gBase + c];

    #pragma unroll
    for (int r = 0; r < 8; r++) {
        size_t row  = (size_t)t0 + mBase + r;
        float* orow = g_ig + ((size_t)h * T_TOTAL + row) * G3 + g0 + gBase;
        #pragma unroll
        for (int c = 0; c < 8; c++)
            orow[c] = hsum2(acc[r][c]) + bb[c];
    }
}

// ============================================================================
// Kernel 2: one CTA (256 threads) per chain. TWO threads per neuron:
//   A (even tid): full r-row + n-row cols [0,64)   -- computes r, tanh, update
//   B (odd  tid): full z-row (rotated 64) + n-row cols [64,128) -- computes z
// Exchange via shfl_xor(1) (same warp); ONE __syncthreads per step.
// PING-PONGED double h buffer (read buf, write buf^1) makes the single
// barrier race-free (round-9 bug fix). Each buffer holds two copies of h:
// natural ([0,128)) and rotated-by-64 ([144,272)) so A and B read disjoint
// bank groups with IDENTICAL instructions.
// Block b -> head floor(log2(b+1)) so head 0 (longest) runs in wave 1.
// ============================================================================
__global__ void __launch_bounds__(256, 1)
rnn_kernel(const float* __restrict__ Whh,
           const float* __restrict__ bn,
           float* __restrict__ out) {
    __shared__ __align__(16) float harr[2][272];

    const int tid   = threadIdx.x;
    const int role  = tid & 1;            // 0=A, 1=B
    const int j     = tid >> 1;
    const int b     = blockIdx.x;
    const int head  = 31 - __clz(b + 1);
    const int chunk = b + 1 - (1 << head);
    const int Tc    = T_TOTAL >> head;

    const float* wsrc = Whh + (size_t)head * G3 * H_DIM;
    const int grow = role ? 128 + j : j;   // gate row: A->r, B->z
    const int rot  = role * 64;            // column rotation for B

    // Gate row (rotated for B so it pairs with B's rotated h stream).
    unsigned long long wg[64];
    {
        const float* src = wsrc + (size_t)grow * H_DIM;
        #pragma unroll
        for (int q = 0; q < 32; q++) {
            int colbase = (4 * q + rot) & 127;
            float4 v = *(const float4*)(src + colbase);
            wg[2 * q]     = pack2(v.x, v.y);
            wg[2 * q + 1] = pack2(v.z, v.w);
        }
    }
    // n-row half: A cols [0,64), B cols [64,128).
    unsigned long long wn[32];
    {
        const float* src = wsrc + (size_t)(256 + j) * H_DIM + rot;
        #pragma unroll
        for (int q = 0; q < 16; q++) {
            float4 v = *(const float4*)(src + 4 * q);
            wn[2 * q]     = pack2(v.x, v.y);
            wn[2 * q + 1] = pack2(v.z, v.w);
        }
    }

    const float bnj = bn[head * H_DIM + j];
    const unsigned long long n_init = (role == 0) ? pack2(bnj, 0.f) : 0ull;

    const float* igp  = g_ig + ((size_t)head * T_TOTAL + (size_t)chunk * Tc) * G3;
    const float* ptr0 = igp + grow;        // own gate ig (r or z)
    const float* ptr1 = igp + 256 + j;     // ig_n (used by A)
    float*       outp = out + (size_t)chunk * Tc * OUT_COLS + head * H_DIM + j;

    float ig0 = __ldcs(ptr0);
    float ig1 = __ldcs(ptr1);
    float hprev = 0.f;
    int   buf   = 0;

    for (int i = tid; i < 272; i += 256) harr[0][i] = 0.f;
    __syncthreads();

    const int rbase = role ? 144 : 0;      // h stream base within a buffer
    const int wpos_rot = 144 + ((j + 64) & 127);

    #pragma unroll 1
    for (int t = 0; t < Tc; t++) {
        // Prefetch next step's input gates (array slack covers the last step).
        float p0 = __ldcs(ptr0 + G3);
        float p1 = __ldcs(ptr1 + G3);

        unsigned long long g0 = pack2(ig0, 0.f), g1 = 0ull;
        unsigned long long n0 = n_init,          n1 = 0ull;

        // Dot phase: 8 chunks of 16 floats. wn active on chunks 0-3 only
        // (A: h[0..63], B: h[64..127] via rotation) — identical instructions
        // for both roles.
        const ulonglong2* hs = (const ulonglong2*)(harr[buf] + rbase);
        #pragma unroll
        for (int q = 0; q < 8; q++) {
            ulonglong2 v0 = hs[4 * q + 0];
            ulonglong2 v1 = hs[4 * q + 1];
            ulonglong2 v2 = hs[4 * q + 2];
            ulonglong2 v3 = hs[4 * q + 3];
            ffma2(g0, wg[8 * q + 0], v0.x);
            ffma2(g1, wg[8 * q + 1], v0.y);
            ffma2(g0, wg[8 * q + 2], v1.x);
            ffma2(g1, wg[8 * q + 3], v1.y);
            ffma2(g0, wg[8 * q + 4], v2.x);
            ffma2(g1, wg[8 * q + 5], v2.y);
            ffma2(g0, wg[8 * q + 6], v3.x);
            ffma2(g1, wg[8 * q + 7], v3.y);
            if (q < 4) {
                ffma2(n0, wn[8 * q + 0], v0.x);
                ffma2(n1, wn[8 * q + 1], v0.y);
                ffma2(n0, wn[8 * q + 2], v1.x);
                ffma2(n1, wn[8 * q + 3], v1.y);
                ffma2(n0, wn[8 * q + 4], v2.x);
                ffma2(n1, wn[8 * q + 5], v2.y);
                ffma2(n0, wn[8 * q + 6], v3.x);
                ffma2(n1, wn[8 * q + 7], v3.y);
            }
        }

        // n half-dot exchange first (starts shfl early), then sigmoids.
        float dnh = hsum2(n0) + hsum2(n1);
        float dn  = dnh + __shfl_xor_sync(0xffffffffu, dnh, 1);

        float dg = hsum2(g0) + hsum2(g1);      // ig already folded in
        float g  = fast_sigmoid(dg);           // A: r,  B: z
        float zv = __shfl_xor_sync(0xffffffffu, g, 1);  // A receives z

        if (role == 0) {
            float n    = fast_tanh(ig1 + g * dn);   // bn already inside dn
            float hnew = n + zv * (hprev - n);
            harr[buf ^ 1][j]        = hnew;
            harr[buf ^ 1][wpos_rot] = hnew;
            __stcs(outp, hnew);
            hprev = hnew;
        }

        __syncthreads();   // h(t+1) published into the other buffer

        buf ^= 1;
        ig0 = p0; ig1 = p1;
        ptr0 += G3; ptr1 += G3;
        outp += OUT_COLS;
    }
}

// ============================================================================
// Launch: GEMM (ig precompute) then recurrence; same stream => ordered.
// ============================================================================
extern "C" void kernel_launch(void* const* d_in, const int* in_sizes, int n_in,
                              void* d_out, int out_size) {
    const float* x   = (const float*)d_in[0];
    const float* Wih = (const float*)d_in[1];
    const float* Whh = (const float*)d_in[2];
    const float* bb  = (const float*)d_in[3];
    const float* bn  = (const float*)d_in[4];
    float* out = (float*)d_out;

    cudaFuncSetAttribute(gemm_ig_kernel,
                         cudaFuncAttributeMaxDynamicSharedMemorySize, GEMM_SMEM);

    gemm_ig_kernel<<<dim3(512, 3, 8), 256, GEMM_SMEM>>>(x, Wih, bb);
    rnn_kernel<<<255, 256>>>(Whh, bn, out);
}